// round 5
// baseline (speedup 1.0000x reference)
#include <cuda_runtime.h>
#include <math.h>
#include <stdint.h>

#define BB 32
#define FF 4096
#define HH 32
#define DD 128
#define LL 8192
#define NSPLIT 16
#define CH (LL/NSPLIT)          /* 512 */
#define TL 64                   /* attention l-tile */
#define SCALE 0.08838834764831845f

/* ---------------- scratch ------------------------------------------------ */
__device__ float g_q[BB*HH*DD];
__device__ float g_k[BB*DD];
__device__ float g_v[BB*DD];
__device__ float g_attn[BB*HH*DD];
__device__ float g_pm[BB*NSPLIT*HH];
__device__ float g_psum[BB*NSPLIT*HH];
__device__ float g_po[BB*NSPLIT*HH*DD];
__device__ float g_freq[64];

/* ---------------- helpers ------------------------------------------------ */
__device__ __forceinline__ uint32_t s2u(const void* p) {
    return (uint32_t)__cvta_generic_to_shared(p);
}
__device__ __forceinline__ void cpa16(uint32_t s, const void* g) {
    asm volatile("cp.async.cg.shared.global [%0], [%1], 16;" :: "r"(s), "l"(g));
}
__device__ __forceinline__ void cpcommit() { asm volatile("cp.async.commit_group;"); }
__device__ __forceinline__ void cpwait0()  { asm volatile("cp.async.wait_group 0;"); }
__device__ __forceinline__ void cpwait1()  { asm volatile("cp.async.wait_group 1;"); }

__device__ __forceinline__ uint32_t f2tf(float x) {
    uint32_t r; asm("cvt.rna.tf32.f32 %0, %1;" : "=r"(r) : "f"(x)); return r;
}
__device__ __forceinline__ float tff(float x) { return __uint_as_float(f2tf(x)); }
__device__ __forceinline__ void mma8(float* d, const uint32_t* a, const uint32_t* b) {
    asm volatile("mma.sync.aligned.m16n8k8.row.col.f32.tf32.tf32.f32 "
        "{%0,%1,%2,%3},{%4,%5,%6,%7},{%8,%9},{%0,%1,%2,%3};"
        : "+f"(d[0]), "+f"(d[1]), "+f"(d[2]), "+f"(d[3])
        : "r"(a[0]), "r"(a[1]), "r"(a[2]), "r"(a[3]), "r"(b[0]), "r"(b[1]));
}

/* ---------------- zero + freq table -------------------------------------- */
__global__ void zero_kernel(float* __restrict__ out) {
    int i = blockIdx.x * 256 + threadIdx.x;
    g_q[i] = 0.f;
    out[i] = 0.f;
    if (i < BB*DD) { g_k[i] = 0.f; g_v[i] = 0.f; }
    if (i < 64) g_freq[i] = (float)exp(-(double)i * 0.14391156831212787);
}

/* ---------------- tensor GEMM (3xTF32): C[32,N] += A[32,4096]*W[4096,N] -- */
#define SPLITK 8
#define KSL (FF/SPLITK)
__global__ __launch_bounds__(256) void tgemm32(
        const float* __restrict__ A, const float* __restrict__ W,
        float* __restrict__ C, int N) {
    extern __shared__ float sm[];
    float* As = sm;
    float* Ws = sm + 16896;
    uint32_t ws_u = s2u(Ws);

    int n0 = blockIdx.x * 256;
    int k0 = blockIdx.y * KSL;
    int t = threadIdx.x, wp = t >> 5, lane = t & 31;
    int g = lane >> 2, c = lane & 3;

#pragma unroll
    for (int p = 0; p < 64; p++) {
        int i = t + p * 256;
        int m = i >> 9, k = i & 511;
        As[k * 33 + m] = A[m * FF + k0 + k];
    }
    auto loadW = [&](int kb, int buf) {
        const float* src = W + (size_t)(k0 + kb * 32) * N + n0;
#pragma unroll
        for (int p = 0; p < 8; p++) {
            int ci = t + p * 256;
            int kk = ci >> 6, u = ci & 63;
            cpa16(ws_u + (uint32_t)((buf * 32 + kk) * 264 + 4 * u) * 4,
                  src + (size_t)kk * N + 4 * u);
        }
        cpcommit();
    };
    loadW(0, 0);

    float acc[2][4][4];
#pragma unroll
    for (int mt = 0; mt < 2; mt++)
#pragma unroll
        for (int nt = 0; nt < 4; nt++)
#pragma unroll
            for (int r = 0; r < 4; r++) acc[mt][nt][r] = 0.f;

    for (int kb = 0; kb < 16; kb++) {
        cpwait0();
        __syncthreads();
        if (kb < 15) loadW(kb + 1, (kb + 1) & 1);
        const float* wsb = Ws + (kb & 1) * 32 * 264;

#pragma unroll
        for (int ks = 0; ks < 4; ks++) {
            int kg = kb * 32 + ks * 8;
            uint32_t ahi[2][4], alo[2][4];
#pragma unroll
            for (int mt = 0; mt < 2; mt++) {
                float a0 = As[(kg + c)     * 33 + mt * 16 + g];
                float a1 = As[(kg + c)     * 33 + mt * 16 + g + 8];
                float a2 = As[(kg + c + 4) * 33 + mt * 16 + g];
                float a3 = As[(kg + c + 4) * 33 + mt * 16 + g + 8];
                ahi[mt][0] = f2tf(a0); alo[mt][0] = f2tf(a0 - __uint_as_float(ahi[mt][0]));
                ahi[mt][1] = f2tf(a1); alo[mt][1] = f2tf(a1 - __uint_as_float(ahi[mt][1]));
                ahi[mt][2] = f2tf(a2); alo[mt][2] = f2tf(a2 - __uint_as_float(ahi[mt][2]));
                ahi[mt][3] = f2tf(a3); alo[mt][3] = f2tf(a3 - __uint_as_float(ahi[mt][3]));
            }
#pragma unroll
            for (int nt = 0; nt < 4; nt++) {
                float b0 = wsb[(ks * 8 + c)     * 264 + wp * 32 + nt * 8 + g];
                float b1 = wsb[(ks * 8 + c + 4) * 264 + wp * 32 + nt * 8 + g];
                uint32_t bhi[2], blo[2];
                bhi[0] = f2tf(b0); blo[0] = f2tf(b0 - __uint_as_float(bhi[0]));
                bhi[1] = f2tf(b1); blo[1] = f2tf(b1 - __uint_as_float(bhi[1]));
#pragma unroll
                for (int mt = 0; mt < 2; mt++) {
                    mma8(acc[mt][nt], ahi[mt], bhi);
                    mma8(acc[mt][nt], ahi[mt], blo);
                    mma8(acc[mt][nt], alo[mt], bhi);
                }
            }
        }
        __syncthreads();
    }
#pragma unroll
    for (int mt = 0; mt < 2; mt++)
#pragma unroll
        for (int nt = 0; nt < 4; nt++) {
            int row = mt * 16 + g;
            int col = n0 + wp * 32 + nt * 8 + 2 * c;
            atomicAdd(&C[(row)     * N + col],     acc[mt][nt][0]);
            atomicAdd(&C[(row)     * N + col + 1], acc[mt][nt][1]);
            atomicAdd(&C[(row + 8) * N + col],     acc[mt][nt][2]);
            atomicAdd(&C[(row + 8) * N + col + 1], acc[mt][nt][3]);
        }
}

/* ---------------- k/v projection ----------------------------------------- */
__global__ __launch_bounds__(256) void kvproj(
        const float* __restrict__ A, const float* __restrict__ Wk,
        const float* __restrict__ Wv) {
    __shared__ float As[32][36];
    __shared__ float Ws[32][132];
    const float* W = blockIdx.x ? Wv : Wk;
    float* C = blockIdx.x ? g_v : g_k;
    int k0 = blockIdx.y * 128;
    int t = threadIdx.x;
    int mi = t >> 5, ni = t & 31;
    float acc[4][4];
#pragma unroll
    for (int i = 0; i < 4; i++)
#pragma unroll
        for (int j = 0; j < 4; j++) acc[i][j] = 0.f;

    for (int kb = 0; kb < 128; kb += 32) {
        int kg = k0 + kb;
#pragma unroll
        for (int p = 0; p < 4; p++) {
            int i = t + p * 256;
            As[i & 31][i >> 5] = A[(i >> 5) * FF + kg + (i & 31)];
        }
#pragma unroll
        for (int p = 0; p < 4; p++) {
            int i = t + p * 256;
            int kk = i >> 5, nq = i & 31;
            *(float4*)&Ws[kk][nq * 4] = *(const float4*)&W[(kg + kk) * DD + nq * 4];
        }
        __syncthreads();
#pragma unroll
        for (int kk = 0; kk < 32; kk++) {
            float4 a = *(float4*)&As[kk][mi * 4];
            float4 w = *(float4*)&Ws[kk][ni * 4];
            acc[0][0] += a.x*w.x; acc[0][1] += a.x*w.y; acc[0][2] += a.x*w.z; acc[0][3] += a.x*w.w;
            acc[1][0] += a.y*w.x; acc[1][1] += a.y*w.y; acc[1][2] += a.y*w.z; acc[1][3] += a.y*w.w;
            acc[2][0] += a.z*w.x; acc[2][1] += a.z*w.y; acc[2][2] += a.z*w.z; acc[2][3] += a.z*w.w;
            acc[3][0] += a.w*w.x; acc[3][1] += a.w*w.y; acc[3][2] += a.w*w.z; acc[3][3] += a.w*w.w;
        }
        __syncthreads();
    }
#pragma unroll
    for (int i = 0; i < 4; i++)
#pragma unroll
        for (int j = 0; j < 4; j++)
            atomicAdd(&C[(mi * 4 + i) * DD + ni * 4 + j], acc[i][j]);
}

/* ---------------- flash-decode attention (tensor cores, v2) ---------------
 * grid (B, NSPLIT), 256 thr = 8 warps, TL=64, 2 CTAs/SM (smem 113,152 B).
 * QK: A = q [h32][d] (2-term split, fragment-packed), B = K [d][l] single-TF32.
 *     warp w -> l cols [8w, 8w+8).
 * PV: A = p [h32][l] single-TF32, B = V [l][d] 2-term (v split on the fly).
 *     warp w -> d cols [16w, 16w+16).
 * RoPE for q fused into the prologue; k roped on-the-fly at the hot column.
 * smem floats: qfh 4096 | qfl 4096 | psh 32x68 (col 64 = corr) |
 *              ks 128x72 | vs 128x68                                       */
#define LDP 68
#define LDKS 72
#define LDVS 68
__global__ __launch_bounds__(256, 2) void attn_kernel(
        const float* __restrict__ Kc, const float* __restrict__ Vc,
        const int* __restrict__ ci) {
    extern __shared__ float sm[];
    float4* qfh4 = (float4*)sm;                 /* 1024 float4 */
    float4* qfl4 = qfh4 + 1024;                 /* 1024 float4 */
    float*  psh  = sm + 8192;                   /* 2176 */
    float*  ks   = sm + 10368;                  /* 9216 */
    float*  vs   = sm + 19584;                  /* 8704 */
    uint32_t ks_u = s2u(ks), vs_u = s2u(vs);

    int b = blockIdx.x, sp = blockIdx.y;
    int idx = ci[b];
    int c0  = sp * CH;
    int t = threadIdx.x, w = t >> 5, lane = t & 31;
    int g = lane >> 2, c = lane & 3;

    int ntiles = 0;
    if (c0 <= idx) ntiles = (min(idx + 1 - c0, CH) + TL - 1) >> 6;

    const float* Kb = Kc + (size_t)b * DD * LL;
    const float* Vb = Vc + (size_t)b * DD * LL;

    /* prologue prefetch of tile 0 (K then V, separate groups) */
    if (ntiles > 0) {
#pragma unroll
        for (int p = 0; p < 8; p++) {
            int i = t + p * 256; int d = i >> 4, u = i & 15;
            cpa16(ks_u + (uint32_t)(d * LDKS + 4 * u) * 4, Kb + (size_t)d * LL + c0 + 4 * u);
        }
        cpcommit();
#pragma unroll
        for (int p = 0; p < 8; p++) {
            int i = t + p * 256; int d = i >> 4, u = i & 15;
            cpa16(vs_u + (uint32_t)(d * LDVS + 4 * u) * 4, Vb + (size_t)d * LL + c0 + 4 * u);
        }
        cpcommit();
    }

    /* q -> rope -> scale -> split -> fragment-packed (fid = kd*64+mt*32+c*8+g) */
    float pos = (float)idx;
#pragma unroll
    for (int p = 0; p < 4; p++) {
        int fid = p * 256 + t;
        int kd = fid >> 6, mt = (fid >> 5) & 1, cc = (fid >> 3) & 3, gg = fid & 7;
        int r0 = mt * 16 + gg, r1 = r0 + 8;
        const float* qb = g_q + b * HH * DD;
        float4 hi, lo;
        float e[4];
#pragma unroll
        for (int dj = 0; dj < 2; dj++) {
            int dcol = 8 * kd + cc + 4 * dj;
            float si, co;
            sincosf(pos * g_freq[dcol & 63], &si, &co);
#pragma unroll
            for (int rj = 0; rj < 2; rj++) {
                int r = rj ? r1 : r0;
                float a = qb[r * DD + dcol];
                float o = qb[r * DD + (dcol ^ 64)];
                float v = (dcol < 64) ? (a * co - o * si) : (a * co + o * si);
                e[dj * 2 + rj] = v * SCALE;
            }
        }
        hi.x = tff(e[0]); lo.x = tff(e[0] - hi.x);
        hi.y = tff(e[1]); lo.y = tff(e[1] - hi.y);
        hi.z = tff(e[2]); lo.z = tff(e[2] - hi.z);
        hi.w = tff(e[3]); lo.w = tff(e[3] - hi.w);
        qfh4[fid] = hi;
        qfl4[fid] = lo;
    }

    float acco[2][2][4];
#pragma unroll
    for (int mt = 0; mt < 2; mt++)
#pragma unroll
        for (int nt = 0; nt < 2; nt++)
#pragma unroll
            for (int r = 0; r < 4; r++) acco[mt][nt][r] = 0.f;
    float m_r[4] = {-1e30f, -1e30f, -1e30f, -1e30f};
    float s_r[4] = {0.f, 0.f, 0.f, 0.f};

    for (int it = 0; it < ntiles; it++) {
        int l0 = c0 + it * TL;
        int hot = (l0 <= idx) && (idx < l0 + TL);
        int li = idx - l0;

        cpwait1();            /* K tile ready (V may still be in flight) */
        __syncthreads();
        if (hot) {
            if (t < 128) {    /* roped k folded into the hot column */
                float si, co;
                sincosf(pos * g_freq[t & 63], &si, &co);
                float a = g_k[b * DD + t];
                float o = g_k[b * DD + (t ^ 64)];
                float kv = (t < 64) ? (a * co - o * si) : (a * co + o * si);
                ks[t * LDKS + li] += kv;
            }
            __syncthreads();
        }

        /* ---- QK: per warp n=8 l-cols ---- */
        float accq[2][4];
#pragma unroll
        for (int mt = 0; mt < 2; mt++)
#pragma unroll
            for (int r = 0; r < 4; r++) accq[mt][r] = 0.f;

#pragma unroll
        for (int kd = 0; kd < 16; kd++) {
            float4 ah0 = qfh4[(kd * 2 + 0) * 32 + c * 8 + g];
            float4 ah1 = qfh4[(kd * 2 + 1) * 32 + c * 8 + g];
            float4 al0 = qfl4[(kd * 2 + 0) * 32 + c * 8 + g];
            float4 al1 = qfl4[(kd * 2 + 1) * 32 + c * 8 + g];
            float b0 = ks[(kd * 8 + c)     * LDKS + w * 8 + g];
            float b1 = ks[(kd * 8 + c + 4) * LDKS + w * 8 + g];
            uint32_t bh[2] = {f2tf(b0), f2tf(b1)};
            mma8(accq[0], (const uint32_t*)&ah0, bh);
            mma8(accq[0], (const uint32_t*)&al0, bh);
            mma8(accq[1], (const uint32_t*)&ah1, bh);
            mma8(accq[1], (const uint32_t*)&al1, bh);
        }
        /* logits -> psh */
#pragma unroll
        for (int mt = 0; mt < 2; mt++) {
            int r0 = mt * 16 + g, cb = w * 8 + 2 * c;
            psh[r0 * LDP + cb]           = accq[mt][0];
            psh[r0 * LDP + cb + 1]       = accq[mt][1];
            psh[(r0 + 8) * LDP + cb]     = accq[mt][2];
            psh[(r0 + 8) * LDP + cb + 1] = accq[mt][3];
        }
        __syncthreads();

        /* prefetch next K (ks free) */
        if (it + 1 < ntiles) {
            int l0n = l0 + TL;
#pragma unroll
            for (int p = 0; p < 8; p++) {
                int i = t + p * 256; int d = i >> 4, u = i & 15;
                cpa16(ks_u + (uint32_t)(d * LDKS + 4 * u) * 4, Kb + (size_t)d * LL + l0n + 4 * u);
            }
            cpcommit();
        }

        /* ---- softmax: warp w owns heads 4w..4w+3; lane covers l=2*lane ---- */
#pragma unroll
        for (int hj = 0; hj < 4; hj++) {
            int h = 4 * w + hj;
            float2 f = *(float2*)&psh[h * LDP + 2 * lane];
            if (l0 + TL - 1 > idx) {
                int lb = l0 + 2 * lane;
                if (lb     > idx) f.x = -1e30f;
                if (lb + 1 > idx) f.y = -1e30f;
            }
            float tm = fmaxf(f.x, f.y);
            tm = fmaxf(tm, __shfl_xor_sync(0xffffffffu, tm, 16));
            tm = fmaxf(tm, __shfl_xor_sync(0xffffffffu, tm, 8));
            tm = fmaxf(tm, __shfl_xor_sync(0xffffffffu, tm, 4));
            tm = fmaxf(tm, __shfl_xor_sync(0xffffffffu, tm, 2));
            tm = fmaxf(tm, __shfl_xor_sync(0xffffffffu, tm, 1));
            float mn = fmaxf(m_r[hj], tm);
            float co = __expf(m_r[hj] - mn);
            float p0 = __expf(f.x - mn), p1 = __expf(f.y - mn);
            float ls = p0 + p1;
            ls += __shfl_xor_sync(0xffffffffu, ls, 16);
            ls += __shfl_xor_sync(0xffffffffu, ls, 8);
            ls += __shfl_xor_sync(0xffffffffu, ls, 4);
            ls += __shfl_xor_sync(0xffffffffu, ls, 2);
            ls += __shfl_xor_sync(0xffffffffu, ls, 1);
            s_r[hj] = s_r[hj] * co + ls;
            m_r[hj] = mn;
            float2 pv2 = make_float2(tff(p0), tff(p1));
            *(float2*)&psh[h * LDP + 2 * lane] = pv2;
            if (lane == 0) psh[h * LDP + 64] = co;   /* corr factor */
        }

        cpwait1();            /* V tile ready */
        __syncthreads();      /* probs + corr visible, vs stable */
        if (hot) {
            if (t < 128) vs[t * LDVS + li] += g_v[b * DD + t];
            __syncthreads();
        }

        /* rescale PV accumulators */
        {
            float s0 = psh[(g)      * LDP + 64];
            float s1 = psh[(g + 8)  * LDP + 64];
            float s2 = psh[(g + 16) * LDP + 64];
            float s3 = psh[(g + 24) * LDP + 64];
#pragma unroll
            for (int nt = 0; nt < 2; nt++) {
                acco[0][nt][0] *= s0; acco[0][nt][1] *= s0;
                acco[0][nt][2] *= s1; acco[0][nt][3] *= s1;
                acco[1][nt][0] *= s2; acco[1][nt][1] *= s2;
                acco[1][nt][2] *= s3; acco[1][nt][3] *= s3;
            }
        }

        /* ---- PV: per warp n=16 d-cols ---- */
#pragma unroll
        for (int kl = 0; kl < 8; kl++) {
            uint32_t ap[2][4];
#pragma unroll
            for (int mt = 0; mt < 2; mt++) {
                int ra = (mt * 16 + g) * LDP + kl * 8;
                int rb = (mt * 16 + g + 8) * LDP + kl * 8;
                ap[mt][0] = __float_as_uint(psh[ra + c]);
                ap[mt][1] = __float_as_uint(psh[rb + c]);
                ap[mt][2] = __float_as_uint(psh[ra + c + 4]);
                ap[mt][3] = __float_as_uint(psh[rb + c + 4]);
            }
#pragma unroll
            for (int nt = 0; nt < 2; nt++) {
                int n = w * 16 + nt * 8 + g;
                float v0 = vs[n * LDVS + kl * 8 + c];
                float v1 = vs[n * LDVS + kl * 8 + c + 4];
                uint32_t bh[2], bl[2];
                bh[0] = f2tf(v0); bl[0] = f2tf(v0 - __uint_as_float(bh[0]));
                bh[1] = f2tf(v1); bl[1] = f2tf(v1 - __uint_as_float(bh[1]));
#pragma unroll
                for (int mt = 0; mt < 2; mt++) {
                    mma8(acco[mt][nt], ap[mt], bh);
                    mma8(acco[mt][nt], ap[mt], bl);
                }
            }
        }
        __syncthreads();

        /* prefetch next V (vs free) */
        if (it + 1 < ntiles) {
            int l0n = l0 + TL;
#pragma unroll
            for (int p = 0; p < 8; p++) {
                int i = t + p * 256; int d = i >> 4, u = i & 15;
                cpa16(vs_u + (uint32_t)(d * LDVS + 4 * u) * 4, Vb + (size_t)d * LL + l0n + 4 * u);
            }
            cpcommit();
        }
    }

    /* write split partials */
    int pb = (b * NSPLIT + sp) * HH;
    if (lane == 0) {
#pragma unroll
        for (int hj = 0; hj < 4; hj++) {
            g_pm[pb + 4 * w + hj]   = m_r[hj];
            g_psum[pb + 4 * w + hj] = s_r[hj];
        }
    }
#pragma unroll
    for (int mt = 0; mt < 2; mt++)
#pragma unroll
        for (int nt = 0; nt < 2; nt++) {
            int h0 = mt * 16 + g;
            int dd = w * 16 + nt * 8 + 2 * c;
            g_po[(size_t)(pb + h0) * DD + dd]         = acco[mt][nt][0];
            g_po[(size_t)(pb + h0) * DD + dd + 1]     = acco[mt][nt][1];
            g_po[(size_t)(pb + h0 + 8) * DD + dd]     = acco[mt][nt][2];
            g_po[(size_t)(pb + h0 + 8) * DD + dd + 1] = acco[mt][nt][3];
        }
}

/* ---------------- combine ------------------------------------------------ */
__global__ void combine_kernel() {
    int bh = blockIdx.x;
    int b = bh >> 5, h = bh & 31;
    int d = threadIdx.x;
    float m = -1e30f;
#pragma unroll
    for (int s = 0; s < NSPLIT; s++)
        m = fmaxf(m, g_pm[(b * NSPLIT + s) * HH + h]);
    float S = 0.f, acc = 0.f;
#pragma unroll
    for (int s = 0; s < NSPLIT; s++) {
        int ib = (b * NSPLIT + s) * HH + h;
        float w = __expf(g_pm[ib] - m);
        S   += w * g_psum[ib];
        acc += w * g_po[(size_t)ib * DD + d];
    }
    g_attn[(b * HH + h) * DD + d] = acc / S;
}

/* ---------------- launch ------------------------------------------------- */
extern "C" void kernel_launch(void* const* d_in, const int* in_sizes, int n_in,
                              void* d_out, int out_size) {
    const float* x  = (const float*)d_in[0];
    const float* Kc = (const float*)d_in[1];
    const float* Vc = (const float*)d_in[2];
    const float* Wq = (const float*)d_in[3];
    const float* Wk = (const float*)d_in[4];
    const float* Wv = (const float*)d_in[5];
    const float* Wo = (const float*)d_in[6];
    const int*   ci = (const int*)d_in[7];
    float* out = (float*)d_out;

    float *qp, *ap;
    cudaGetSymbolAddress((void**)&qp, g_q);
    cudaGetSymbolAddress((void**)&ap, g_attn);

    cudaFuncSetAttribute(tgemm32,
                         cudaFuncAttributeMaxDynamicSharedMemorySize, 135168);
    cudaFuncSetAttribute(attn_kernel,
                         cudaFuncAttributeMaxDynamicSharedMemorySize, 113152);

    zero_kernel<<<512, 256>>>(out);
    tgemm32<<<dim3(16, SPLITK), 256, 135168>>>(x, Wq, qp, 4096);
    kvproj<<<dim3(2, 32), 256>>>(x, Wk, Wv);
    attn_kernel<<<dim3(32, NSPLIT), 256, 113152>>>(Kc, Vc, ci);
    combine_kernel<<<1024, 128>>>();
    tgemm32<<<dim3(16, SPLITK), 256, 135168>>>(ap, Wo, out, 4096);
}

// round 6
// speedup vs baseline: 1.1291x; 1.1291x over previous
#include <cuda_runtime.h>
#include <math.h>
#include <stdint.h>

#define BB 32
#define FF 4096
#define HH 32
#define DD 128
#define LL 8192
#define NSPLIT 16
#define CH (LL/NSPLIT)          /* 512 */
#define TLL 256                 /* attention l-tile */
#define LDP 260                 /* psh row stride (col 256 = corr) */
#define SCALE 0.08838834764831845f

/* ---------------- scratch ------------------------------------------------ */
__device__ float g_q[BB*HH*DD];
__device__ float g_k[BB*DD];
__device__ float g_kr[BB*DD];       /* roped k */
__device__ float g_v[BB*DD];
__device__ float g_attn[BB*HH*DD];
__device__ float g_pm[BB*NSPLIT*HH];
__device__ float g_psum[BB*NSPLIT*HH];
__device__ float g_po[BB*NSPLIT*HH*DD];
__device__ float g_freq[64];

/* ---------------- helpers ------------------------------------------------ */
__device__ __forceinline__ uint32_t s2u(const void* p) {
    return (uint32_t)__cvta_generic_to_shared(p);
}
__device__ __forceinline__ void cpa16(uint32_t s, const void* g) {
    asm volatile("cp.async.cg.shared.global [%0], [%1], 16;" :: "r"(s), "l"(g));
}
__device__ __forceinline__ void cpcommit() { asm volatile("cp.async.commit_group;"); }
__device__ __forceinline__ void cpwait0()  { asm volatile("cp.async.wait_group 0;"); }

__device__ __forceinline__ uint32_t f2tf(float x) {
    uint32_t r; asm("cvt.rna.tf32.f32 %0, %1;" : "=r"(r) : "f"(x)); return r;
}
__device__ __forceinline__ float tff(float x) { return __uint_as_float(f2tf(x)); }
__device__ __forceinline__ void mma8(float* d, const uint32_t* a, const uint32_t* b) {
    asm volatile("mma.sync.aligned.m16n8k8.row.col.f32.tf32.tf32.f32 "
        "{%0,%1,%2,%3},{%4,%5,%6,%7},{%8,%9},{%0,%1,%2,%3};"
        : "+f"(d[0]), "+f"(d[1]), "+f"(d[2]), "+f"(d[3])
        : "r"(a[0]), "r"(a[1]), "r"(a[2]), "r"(a[3]), "r"(b[0]), "r"(b[1]));
}

/* ---------------- zero + freq table -------------------------------------- */
__global__ void zero_kernel(float* __restrict__ out) {
    int i = blockIdx.x * 256 + threadIdx.x;
    g_q[i] = 0.f;
    out[i] = 0.f;
    if (i < BB*DD) { g_k[i] = 0.f; g_v[i] = 0.f; }
    if (i < 64) g_freq[i] = (float)exp(-(double)i * 0.14391156831212787);
}

/* ---------------- tensor GEMM (3xTF32): C[32,N] += A[32,4096]*W[4096,N] -- */
#define SPLITK 8
#define KSL (FF/SPLITK)
__global__ __launch_bounds__(256) void tgemm32(
        const float* __restrict__ A, const float* __restrict__ W,
        float* __restrict__ C, int N) {
    extern __shared__ float sm[];
    float* As = sm;
    float* Ws = sm + 16896;
    uint32_t ws_u = s2u(Ws);

    int n0 = blockIdx.x * 256;
    int k0 = blockIdx.y * KSL;
    int t = threadIdx.x, wp = t >> 5, lane = t & 31;
    int g = lane >> 2, c = lane & 3;

#pragma unroll
    for (int p = 0; p < 64; p++) {
        int i = t + p * 256;
        int m = i >> 9, k = i & 511;
        As[k * 33 + m] = A[m * FF + k0 + k];
    }
    auto loadW = [&](int kb, int buf) {
        const float* src = W + (size_t)(k0 + kb * 32) * N + n0;
#pragma unroll
        for (int p = 0; p < 8; p++) {
            int ci = t + p * 256;
            int kk = ci >> 6, u = ci & 63;
            cpa16(ws_u + (uint32_t)((buf * 32 + kk) * 264 + 4 * u) * 4,
                  src + (size_t)kk * N + 4 * u);
        }
        cpcommit();
    };
    loadW(0, 0);

    float acc[2][4][4];
#pragma unroll
    for (int mt = 0; mt < 2; mt++)
#pragma unroll
        for (int nt = 0; nt < 4; nt++)
#pragma unroll
            for (int r = 0; r < 4; r++) acc[mt][nt][r] = 0.f;

    for (int kb = 0; kb < 16; kb++) {
        cpwait0();
        __syncthreads();
        if (kb < 15) loadW(kb + 1, (kb + 1) & 1);
        const float* wsb = Ws + (kb & 1) * 32 * 264;

#pragma unroll
        for (int ks = 0; ks < 4; ks++) {
            int kg = kb * 32 + ks * 8;
            uint32_t ahi[2][4], alo[2][4];
#pragma unroll
            for (int mt = 0; mt < 2; mt++) {
                float a0 = As[(kg + c)     * 33 + mt * 16 + g];
                float a1 = As[(kg + c)     * 33 + mt * 16 + g + 8];
                float a2 = As[(kg + c + 4) * 33 + mt * 16 + g];
                float a3 = As[(kg + c + 4) * 33 + mt * 16 + g + 8];
                ahi[mt][0] = f2tf(a0); alo[mt][0] = f2tf(a0 - __uint_as_float(ahi[mt][0]));
                ahi[mt][1] = f2tf(a1); alo[mt][1] = f2tf(a1 - __uint_as_float(ahi[mt][1]));
                ahi[mt][2] = f2tf(a2); alo[mt][2] = f2tf(a2 - __uint_as_float(ahi[mt][2]));
                ahi[mt][3] = f2tf(a3); alo[mt][3] = f2tf(a3 - __uint_as_float(ahi[mt][3]));
            }
#pragma unroll
            for (int nt = 0; nt < 4; nt++) {
                float b0 = wsb[(ks * 8 + c)     * 264 + wp * 32 + nt * 8 + g];
                float b1 = wsb[(ks * 8 + c + 4) * 264 + wp * 32 + nt * 8 + g];
                uint32_t bhi[2], blo[2];
                bhi[0] = f2tf(b0); blo[0] = f2tf(b0 - __uint_as_float(bhi[0]));
                bhi[1] = f2tf(b1); blo[1] = f2tf(b1 - __uint_as_float(bhi[1]));
#pragma unroll
                for (int mt = 0; mt < 2; mt++) {
                    mma8(acc[mt][nt], ahi[mt], bhi);
                    mma8(acc[mt][nt], ahi[mt], blo);
                    mma8(acc[mt][nt], alo[mt], bhi);
                }
            }
        }
        __syncthreads();
    }
#pragma unroll
    for (int mt = 0; mt < 2; mt++)
#pragma unroll
        for (int nt = 0; nt < 4; nt++) {
            int row = mt * 16 + g;
            int col = n0 + wp * 32 + nt * 8 + 2 * c;
            atomicAdd(&C[(row)     * N + col],     acc[mt][nt][0]);
            atomicAdd(&C[(row)     * N + col + 1], acc[mt][nt][1]);
            atomicAdd(&C[(row + 8) * N + col],     acc[mt][nt][2]);
            atomicAdd(&C[(row + 8) * N + col + 1], acc[mt][nt][3]);
        }
}

/* ---------------- k/v projection ----------------------------------------- */
__global__ __launch_bounds__(256) void kvproj(
        const float* __restrict__ A, const float* __restrict__ Wk,
        const float* __restrict__ Wv) {
    __shared__ float As[32][36];
    __shared__ float Ws[32][132];
    const float* W = blockIdx.x ? Wv : Wk;
    float* C = blockIdx.x ? g_v : g_k;
    int k0 = blockIdx.y * 128;
    int t = threadIdx.x;
    int mi = t >> 5, ni = t & 31;
    float acc[4][4];
#pragma unroll
    for (int i = 0; i < 4; i++)
#pragma unroll
        for (int j = 0; j < 4; j++) acc[i][j] = 0.f;

    for (int kb = 0; kb < 128; kb += 32) {
        int kg = k0 + kb;
#pragma unroll
        for (int p = 0; p < 4; p++) {
            int i = t + p * 256;
            As[i & 31][i >> 5] = A[(i >> 5) * FF + kg + (i & 31)];
        }
#pragma unroll
        for (int p = 0; p < 4; p++) {
            int i = t + p * 256;
            int kk = i >> 5, nq = i & 31;
            *(float4*)&Ws[kk][nq * 4] = *(const float4*)&W[(kg + kk) * DD + nq * 4];
        }
        __syncthreads();
#pragma unroll
        for (int kk = 0; kk < 32; kk++) {
            float4 a = *(float4*)&As[kk][mi * 4];
            float4 w = *(float4*)&Ws[kk][ni * 4];
            acc[0][0] += a.x*w.x; acc[0][1] += a.x*w.y; acc[0][2] += a.x*w.z; acc[0][3] += a.x*w.w;
            acc[1][0] += a.y*w.x; acc[1][1] += a.y*w.y; acc[1][2] += a.y*w.z; acc[1][3] += a.y*w.w;
            acc[2][0] += a.z*w.x; acc[2][1] += a.z*w.y; acc[2][2] += a.z*w.z; acc[2][3] += a.z*w.w;
            acc[3][0] += a.w*w.x; acc[3][1] += a.w*w.y; acc[3][2] += a.w*w.z; acc[3][3] += a.w*w.w;
        }
        __syncthreads();
    }
#pragma unroll
    for (int i = 0; i < 4; i++)
#pragma unroll
        for (int j = 0; j < 4; j++)
            atomicAdd(&C[(mi * 4 + i) * DD + ni * 4 + j], acc[i][j]);
}

/* ---------------- rope k -> g_kr ----------------------------------------- */
__global__ void krope_kernel(const int* __restrict__ ci) {
    int b = blockIdx.x, d = threadIdx.x;   /* 128 threads */
    float pos = (float)ci[b];
    float s, c;
    sincosf(pos * g_freq[d & 63], &s, &c);
    float a = g_k[b * DD + d];
    float o = g_k[b * DD + (d ^ 64)];
    g_kr[b * DD + d] = (d < 64) ? (a * c - o * s) : (a * c + o * s);
}

/* ---------------- flash-decode attention (tensor cores, direct-LDG KV) ----
 * grid (B, NSPLIT), 256 thr = 8 warps, TL=256, <=2 tiles per CTA.
 * QK: A = q (2-term, fragment-packed smem), B = K[d][l] gathered straight
 *     from GMEM as fragments (single TF32). warp w -> l [32w, 32w+32).
 * PV: A = p (single TF32, via psh), B = V[l][d] gathered from GMEM (2-term).
 *     warp w -> d [16w, 16w+16).
 * Decode-step cache update folded in as predicated adds (g_kr / g_v).
 * smem floats: qfh 4096 | qfl 4096 | psh 32*260  -> 66048 B               */
__global__ __launch_bounds__(256) void attn_kernel(
        const float* __restrict__ Kc, const float* __restrict__ Vc,
        const int* __restrict__ ci) {
    extern __shared__ float sm[];
    float4* qfh4 = (float4*)sm;                 /* 1024 float4 */
    float4* qfl4 = qfh4 + 1024;                 /* 1024 float4 */
    float*  psh  = sm + 8192;                   /* 32*260 */

    int b = blockIdx.x, sp = blockIdx.y;
    int idx = ci[b];
    int c0  = sp * CH;
    int t = threadIdx.x, w = t >> 5, lane = t & 31;
    int g = lane >> 2, c = lane & 3;

    int ntiles = 0;
    if (c0 <= idx) ntiles = (min(idx + 1 - c0, CH) + TLL - 1) >> 8;

    const float* Kb = Kc + (size_t)b * DD * LL;
    const float* Vb = Vc + (size_t)b * DD * LL;

    /* q -> rope -> scale -> split -> fragment-packed (fid = kd*64+mt*32+c*8+g) */
    float pos = (float)idx;
#pragma unroll
    for (int p = 0; p < 4; p++) {
        int fid = p * 256 + t;
        int kd = fid >> 6, mt = (fid >> 5) & 1, cc = (fid >> 3) & 3, gg = fid & 7;
        int r0 = mt * 16 + gg, r1 = r0 + 8;
        const float* qb = g_q + b * HH * DD;
        float4 hi, lo;
        float e[4];
#pragma unroll
        for (int dj = 0; dj < 2; dj++) {
            int dcol = 8 * kd + cc + 4 * dj;
            float si, co;
            sincosf(pos * g_freq[dcol & 63], &si, &co);
#pragma unroll
            for (int rj = 0; rj < 2; rj++) {
                int r = rj ? r1 : r0;
                float a = qb[r * DD + dcol];
                float o = qb[r * DD + (dcol ^ 64)];
                float v = (dcol < 64) ? (a * co - o * si) : (a * co + o * si);
                e[dj * 2 + rj] = v * SCALE;
            }
        }
        hi.x = tff(e[0]); lo.x = tff(e[0] - hi.x);
        hi.y = tff(e[1]); lo.y = tff(e[1] - hi.y);
        hi.z = tff(e[2]); lo.z = tff(e[2] - hi.z);
        hi.w = tff(e[3]); lo.w = tff(e[3] - hi.w);
        qfh4[fid] = hi;
        qfl4[fid] = lo;
    }

    float acco[2][2][4];
#pragma unroll
    for (int mt = 0; mt < 2; mt++)
#pragma unroll
        for (int nt = 0; nt < 2; nt++)
#pragma unroll
            for (int r = 0; r < 4; r++) acco[mt][nt][r] = 0.f;
    float m_r[4] = {-1e30f, -1e30f, -1e30f, -1e30f};
    float s_r[4] = {0.f, 0.f, 0.f, 0.f};

    __syncthreads();

    for (int it = 0; it < ntiles; it++) {
        int lt = c0 + it * TLL;
        int hot = (lt <= idx) && (idx < lt + TLL);

        /* ---- QK: B-fragments straight from GMEM ---- */
        float accq[2][4][4];
#pragma unroll
        for (int mt = 0; mt < 2; mt++)
#pragma unroll
            for (int nt = 0; nt < 4; nt++)
#pragma unroll
                for (int r = 0; r < 4; r++) accq[mt][nt][r] = 0.f;

#pragma unroll 4
        for (int kd = 0; kd < 16; kd++) {
            float4 ah0 = qfh4[kd * 64 +      c * 8 + g];
            float4 ah1 = qfh4[kd * 64 + 32 + c * 8 + g];
            float4 al0 = qfl4[kd * 64 +      c * 8 + g];
            float4 al1 = qfl4[kd * 64 + 32 + c * 8 + g];
            const float* k0p = Kb + (size_t)(kd * 8 + c) * LL + lt + w * 32 + g;
            const float* k1p = k0p + 4 * LL;
#pragma unroll
            for (int nt = 0; nt < 4; nt++) {
                float b0f = k0p[nt * 8];
                float b1f = k1p[nt * 8];
                if (hot && (lt + w * 32 + nt * 8 + g == idx)) {
                    b0f += g_kr[b * DD + kd * 8 + c];
                    b1f += g_kr[b * DD + kd * 8 + c + 4];
                }
                uint32_t bb[2] = {f2tf(b0f), f2tf(b1f)};
                mma8(accq[0][nt], (const uint32_t*)&ah0, bb);
                mma8(accq[0][nt], (const uint32_t*)&al0, bb);
                mma8(accq[1][nt], (const uint32_t*)&ah1, bb);
                mma8(accq[1][nt], (const uint32_t*)&al1, bb);
            }
        }
        /* logits -> psh */
#pragma unroll
        for (int mt = 0; mt < 2; mt++)
#pragma unroll
            for (int nt = 0; nt < 4; nt++) {
                int r0 = mt * 16 + g, cb = w * 32 + nt * 8 + 2 * c;
                psh[r0 * LDP + cb]           = accq[mt][nt][0];
                psh[r0 * LDP + cb + 1]       = accq[mt][nt][1];
                psh[(r0 + 8) * LDP + cb]     = accq[mt][nt][2];
                psh[(r0 + 8) * LDP + cb + 1] = accq[mt][nt][3];
            }
        __syncthreads();

        /* ---- softmax: warp w owns heads 4w..4w+3; lane covers l=8*lane ---- */
#pragma unroll
        for (int hj = 0; hj < 4; hj++) {
            int h = 4 * w + hj;
            float4 fa = *(float4*)&psh[h * LDP + 8 * lane];
            float4 fb = *(float4*)&psh[h * LDP + 8 * lane + 4];
            if (lt + TLL - 1 > idx) {
                int lb = lt + 8 * lane;
                if (lb     > idx) fa.x = -1e30f;
                if (lb + 1 > idx) fa.y = -1e30f;
                if (lb + 2 > idx) fa.z = -1e30f;
                if (lb + 3 > idx) fa.w = -1e30f;
                if (lb + 4 > idx) fb.x = -1e30f;
                if (lb + 5 > idx) fb.y = -1e30f;
                if (lb + 6 > idx) fb.z = -1e30f;
                if (lb + 7 > idx) fb.w = -1e30f;
            }
            float tm = fmaxf(fmaxf(fmaxf(fa.x, fa.y), fmaxf(fa.z, fa.w)),
                             fmaxf(fmaxf(fb.x, fb.y), fmaxf(fb.z, fb.w)));
            tm = fmaxf(tm, __shfl_xor_sync(0xffffffffu, tm, 16));
            tm = fmaxf(tm, __shfl_xor_sync(0xffffffffu, tm, 8));
            tm = fmaxf(tm, __shfl_xor_sync(0xffffffffu, tm, 4));
            tm = fmaxf(tm, __shfl_xor_sync(0xffffffffu, tm, 2));
            tm = fmaxf(tm, __shfl_xor_sync(0xffffffffu, tm, 1));
            float mn = fmaxf(m_r[hj], tm);
            float co = __expf(m_r[hj] - mn);
            float4 pa, pb;
            pa.x = __expf(fa.x - mn); pa.y = __expf(fa.y - mn);
            pa.z = __expf(fa.z - mn); pa.w = __expf(fa.w - mn);
            pb.x = __expf(fb.x - mn); pb.y = __expf(fb.y - mn);
            pb.z = __expf(fb.z - mn); pb.w = __expf(fb.w - mn);
            float ls = (pa.x + pa.y + pa.z + pa.w) + (pb.x + pb.y + pb.z + pb.w);
            ls += __shfl_xor_sync(0xffffffffu, ls, 16);
            ls += __shfl_xor_sync(0xffffffffu, ls, 8);
            ls += __shfl_xor_sync(0xffffffffu, ls, 4);
            ls += __shfl_xor_sync(0xffffffffu, ls, 2);
            ls += __shfl_xor_sync(0xffffffffu, ls, 1);
            s_r[hj] = s_r[hj] * co + ls;
            m_r[hj] = mn;
            pa.x = tff(pa.x); pa.y = tff(pa.y); pa.z = tff(pa.z); pa.w = tff(pa.w);
            pb.x = tff(pb.x); pb.y = tff(pb.y); pb.z = tff(pb.z); pb.w = tff(pb.w);
            *(float4*)&psh[h * LDP + 8 * lane]     = pa;
            *(float4*)&psh[h * LDP + 8 * lane + 4] = pb;
            if (lane == 0) psh[h * LDP + 256] = co;
        }
        __syncthreads();

        /* rescale PV accumulators by per-head corr */
        {
            float s0 = psh[(g)      * LDP + 256];
            float s1 = psh[(g + 8)  * LDP + 256];
            float s2 = psh[(g + 16) * LDP + 256];
            float s3 = psh[(g + 24) * LDP + 256];
#pragma unroll
            for (int nt = 0; nt < 2; nt++) {
                acco[0][nt][0] *= s0; acco[0][nt][1] *= s0;
                acco[0][nt][2] *= s1; acco[0][nt][3] *= s1;
                acco[1][nt][0] *= s2; acco[1][nt][1] *= s2;
                acco[1][nt][2] *= s3; acco[1][nt][3] *= s3;
            }
        }

        /* ---- PV: p from psh (A), V from GMEM (B, 2-term) ---- */
#pragma unroll 4
        for (int kl = 0; kl < 32; kl++) {
            int lb0 = kl * 8 + c;
            uint32_t ap0[4], ap1[4];
            ap0[0] = __float_as_uint(psh[(g)      * LDP + lb0]);
            ap0[1] = __float_as_uint(psh[(g + 8)  * LDP + lb0]);
            ap0[2] = __float_as_uint(psh[(g)      * LDP + lb0 + 4]);
            ap0[3] = __float_as_uint(psh[(g + 8)  * LDP + lb0 + 4]);
            ap1[0] = __float_as_uint(psh[(g + 16) * LDP + lb0]);
            ap1[1] = __float_as_uint(psh[(g + 24) * LDP + lb0]);
            ap1[2] = __float_as_uint(psh[(g + 16) * LDP + lb0 + 4]);
            ap1[3] = __float_as_uint(psh[(g + 24) * LDP + lb0 + 4]);
#pragma unroll
            for (int nt = 0; nt < 2; nt++) {
                int d = w * 16 + nt * 8 + g;
                float v0f = Vb[(size_t)d * LL + lt + lb0];
                float v1f = Vb[(size_t)d * LL + lt + lb0 + 4];
                if (hot) {
                    if (lt + lb0     == idx) v0f += g_v[b * DD + d];
                    if (lt + lb0 + 4 == idx) v1f += g_v[b * DD + d];
                }
                uint32_t bh[2], bl[2];
                bh[0] = f2tf(v0f); bl[0] = f2tf(v0f - __uint_as_float(bh[0]));
                bh[1] = f2tf(v1f); bl[1] = f2tf(v1f - __uint_as_float(bh[1]));
                mma8(acco[0][nt], ap0, bh);
                mma8(acco[0][nt], ap0, bl);
                mma8(acco[1][nt], ap1, bh);
                mma8(acco[1][nt], ap1, bl);
            }
        }
        __syncthreads();   /* psh free for next tile */
    }

    /* write split partials */
    int pb = (b * NSPLIT + sp) * HH;
    if (lane == 0) {
#pragma unroll
        for (int hj = 0; hj < 4; hj++) {
            g_pm[pb + 4 * w + hj]   = m_r[hj];
            g_psum[pb + 4 * w + hj] = s_r[hj];
        }
    }
#pragma unroll
    for (int mt = 0; mt < 2; mt++)
#pragma unroll
        for (int nt = 0; nt < 2; nt++) {
            int h0 = mt * 16 + g;
            int dd = w * 16 + nt * 8 + 2 * c;
            g_po[(size_t)(pb + h0) * DD + dd]         = acco[mt][nt][0];
            g_po[(size_t)(pb + h0) * DD + dd + 1]     = acco[mt][nt][1];
            g_po[(size_t)(pb + h0 + 8) * DD + dd]     = acco[mt][nt][2];
            g_po[(size_t)(pb + h0 + 8) * DD + dd + 1] = acco[mt][nt][3];
        }
}

/* ---------------- combine ------------------------------------------------ */
__global__ void combine_kernel() {
    int bh = blockIdx.x;
    int b = bh >> 5, h = bh & 31;
    int d = threadIdx.x;
    float m = -1e30f;
#pragma unroll
    for (int s = 0; s < NSPLIT; s++)
        m = fmaxf(m, g_pm[(b * NSPLIT + s) * HH + h]);
    float S = 0.f, acc = 0.f;
#pragma unroll
    for (int s = 0; s < NSPLIT; s++) {
        int ib = (b * NSPLIT + s) * HH + h;
        float w = __expf(g_pm[ib] - m);
        S   += w * g_psum[ib];
        acc += w * g_po[(size_t)ib * DD + d];
    }
    g_attn[(b * HH + h) * DD + d] = acc / S;
}

/* ---------------- launch ------------------------------------------------- */
extern "C" void kernel_launch(void* const* d_in, const int* in_sizes, int n_in,
                              void* d_out, int out_size) {
    const float* x  = (const float*)d_in[0];
    const float* Kc = (const float*)d_in[1];
    const float* Vc = (const float*)d_in[2];
    const float* Wq = (const float*)d_in[3];
    const float* Wk = (const float*)d_in[4];
    const float* Wv = (const float*)d_in[5];
    const float* Wo = (const float*)d_in[6];
    const int*   ci = (const int*)d_in[7];
    float* out = (float*)d_out;

    float *qp, *ap;
    cudaGetSymbolAddress((void**)&qp, g_q);
    cudaGetSymbolAddress((void**)&ap, g_attn);

    cudaFuncSetAttribute(tgemm32,
                         cudaFuncAttributeMaxDynamicSharedMemorySize, 135168);
    cudaFuncSetAttribute(attn_kernel,
                         cudaFuncAttributeMaxDynamicSharedMemorySize, 66048);

    zero_kernel<<<512, 256>>>(out);
    tgemm32<<<dim3(16, SPLITK), 256, 135168>>>(x, Wq, qp, 4096);
    kvproj<<<dim3(2, 32), 256>>>(x, Wk, Wv);
    krope_kernel<<<32, 128>>>(ci);
    attn_kernel<<<dim3(32, NSPLIT), 256, 66048>>>(Kc, Vc, ci);
    combine_kernel<<<1024, 128>>>();
    tgemm32<<<dim3(16, SPLITK), 256, 135168>>>(ap, Wo, out, 4096);
}

// round 7
// speedup vs baseline: 1.2621x; 1.1178x over previous
#include <cuda_runtime.h>
#include <math.h>
#include <stdint.h>

#define BB 32
#define FF 4096
#define HH 32
#define DD 128
#define LL 8192
#define NSPLIT 32
#define CH (LL/NSPLIT)          /* 256 */
#define WIN 64
#define LDW 72                  /* K window stride (floats) */
#define LDV 68                  /* V window stride (floats) */
#define LDP 260                 /* psh row stride */
#define BUFF 9216               /* per-buffer floats (128*72) */
#define SCALE 0.08838834764831845f

/* ---------------- scratch ------------------------------------------------ */
__device__ float g_q[BB*HH*DD];
__device__ float g_k[BB*DD];
__device__ float g_v[BB*DD];
__device__ float g_attn[BB*HH*DD];
__device__ float g_pm[BB*NSPLIT*HH];
__device__ float g_psum[BB*NSPLIT*HH];
__device__ float g_po[BB*NSPLIT*HH*DD];   /* 16 MB */
__device__ float g_freq[64];

/* ---------------- helpers ------------------------------------------------ */
__device__ __forceinline__ uint32_t s2u(const void* p) {
    return (uint32_t)__cvta_generic_to_shared(p);
}
__device__ __forceinline__ void cpa16(uint32_t s, const void* g) {
    asm volatile("cp.async.cg.shared.global [%0], [%1], 16;" :: "r"(s), "l"(g));
}
__device__ __forceinline__ void cpcommit() { asm volatile("cp.async.commit_group;"); }
__device__ __forceinline__ void cpwait0()  { asm volatile("cp.async.wait_group 0;"); }
__device__ __forceinline__ void cpwait1()  { asm volatile("cp.async.wait_group 1;"); }

__device__ __forceinline__ uint32_t f2tf(float x) {
    uint32_t r; asm("cvt.rna.tf32.f32 %0, %1;" : "=r"(r) : "f"(x)); return r;
}
__device__ __forceinline__ float tff(float x) { return __uint_as_float(f2tf(x)); }
__device__ __forceinline__ void mma8(float* d, const uint32_t* a, const uint32_t* b) {
    asm volatile("mma.sync.aligned.m16n8k8.row.col.f32.tf32.tf32.f32 "
        "{%0,%1,%2,%3},{%4,%5,%6,%7},{%8,%9},{%0,%1,%2,%3};"
        : "+f"(d[0]), "+f"(d[1]), "+f"(d[2]), "+f"(d[3])
        : "r"(a[0]), "r"(a[1]), "r"(a[2]), "r"(a[3]), "r"(b[0]), "r"(b[1]));
}

/* ---------------- zero + freq table -------------------------------------- */
__global__ void zero_kernel(float* __restrict__ out) {
    int i = blockIdx.x * 256 + threadIdx.x;
    g_q[i] = 0.f;
    out[i] = 0.f;
    if (i < BB*DD) { g_k[i] = 0.f; g_v[i] = 0.f; }
    if (i < 64) g_freq[i] = (float)exp(-(double)i * 0.14391156831212787);
}

/* ---------------- tensor GEMM (3xTF32): C[32,N] += A[32,4096]*W[4096,N] -- */
#define SPLITK 8
#define KSL (FF/SPLITK)
__global__ __launch_bounds__(256) void tgemm32(
        const float* __restrict__ A, const float* __restrict__ W,
        float* __restrict__ C, int N) {
    extern __shared__ float sm[];
    float* As = sm;
    float* Ws = sm + 16896;
    uint32_t ws_u = s2u(Ws);

    int n0 = blockIdx.x * 256;
    int k0 = blockIdx.y * KSL;
    int t = threadIdx.x, wp = t >> 5, lane = t & 31;
    int g = lane >> 2, c = lane & 3;

#pragma unroll
    for (int p = 0; p < 64; p++) {
        int i = t + p * 256;
        int m = i >> 9, k = i & 511;
        As[k * 33 + m] = A[m * FF + k0 + k];
    }
    auto loadW = [&](int kb, int buf) {
        const float* src = W + (size_t)(k0 + kb * 32) * N + n0;
#pragma unroll
        for (int p = 0; p < 8; p++) {
            int ci = t + p * 256;
            int kk = ci >> 6, u = ci & 63;
            cpa16(ws_u + (uint32_t)((buf * 32 + kk) * 264 + 4 * u) * 4,
                  src + (size_t)kk * N + 4 * u);
        }
        cpcommit();
    };
    loadW(0, 0);

    float acc[2][4][4];
#pragma unroll
    for (int mt = 0; mt < 2; mt++)
#pragma unroll
        for (int nt = 0; nt < 4; nt++)
#pragma unroll
            for (int r = 0; r < 4; r++) acc[mt][nt][r] = 0.f;

    for (int kb = 0; kb < 16; kb++) {
        cpwait0();
        __syncthreads();
        if (kb < 15) loadW(kb + 1, (kb + 1) & 1);
        const float* wsb = Ws + (kb & 1) * 32 * 264;

#pragma unroll
        for (int ks = 0; ks < 4; ks++) {
            int kg = kb * 32 + ks * 8;
            uint32_t ahi[2][4], alo[2][4];
#pragma unroll
            for (int mt = 0; mt < 2; mt++) {
                float a0 = As[(kg + c)     * 33 + mt * 16 + g];
                float a1 = As[(kg + c)     * 33 + mt * 16 + g + 8];
                float a2 = As[(kg + c + 4) * 33 + mt * 16 + g];
                float a3 = As[(kg + c + 4) * 33 + mt * 16 + g + 8];
                ahi[mt][0] = f2tf(a0); alo[mt][0] = f2tf(a0 - __uint_as_float(ahi[mt][0]));
                ahi[mt][1] = f2tf(a1); alo[mt][1] = f2tf(a1 - __uint_as_float(ahi[mt][1]));
                ahi[mt][2] = f2tf(a2); alo[mt][2] = f2tf(a2 - __uint_as_float(ahi[mt][2]));
                ahi[mt][3] = f2tf(a3); alo[mt][3] = f2tf(a3 - __uint_as_float(ahi[mt][3]));
            }
#pragma unroll
            for (int nt = 0; nt < 4; nt++) {
                float b0 = wsb[(ks * 8 + c)     * 264 + wp * 32 + nt * 8 + g];
                float b1 = wsb[(ks * 8 + c + 4) * 264 + wp * 32 + nt * 8 + g];
                uint32_t bhi[2], blo[2];
                bhi[0] = f2tf(b0); blo[0] = f2tf(b0 - __uint_as_float(bhi[0]));
                bhi[1] = f2tf(b1); blo[1] = f2tf(b1 - __uint_as_float(bhi[1]));
#pragma unroll
                for (int mt = 0; mt < 2; mt++) {
                    mma8(acc[mt][nt], ahi[mt], bhi);
                    mma8(acc[mt][nt], ahi[mt], blo);
                    mma8(acc[mt][nt], alo[mt], bhi);
                }
            }
        }
        __syncthreads();
    }
#pragma unroll
    for (int mt = 0; mt < 2; mt++)
#pragma unroll
        for (int nt = 0; nt < 4; nt++) {
            int row = mt * 16 + g;
            int col = n0 + wp * 32 + nt * 8 + 2 * c;
            atomicAdd(&C[(row)     * N + col],     acc[mt][nt][0]);
            atomicAdd(&C[(row)     * N + col + 1], acc[mt][nt][1]);
            atomicAdd(&C[(row + 8) * N + col],     acc[mt][nt][2]);
            atomicAdd(&C[(row + 8) * N + col + 1], acc[mt][nt][3]);
        }
}

/* ---------------- k/v projection ----------------------------------------- */
__global__ __launch_bounds__(256) void kvproj(
        const float* __restrict__ A, const float* __restrict__ Wk,
        const float* __restrict__ Wv) {
    __shared__ float As[32][36];
    __shared__ float Ws[32][132];
    const float* W = blockIdx.x ? Wv : Wk;
    float* C = blockIdx.x ? g_v : g_k;
    int k0 = blockIdx.y * 128;
    int t = threadIdx.x;
    int mi = t >> 5, ni = t & 31;
    float acc[4][4];
#pragma unroll
    for (int i = 0; i < 4; i++)
#pragma unroll
        for (int j = 0; j < 4; j++) acc[i][j] = 0.f;

    for (int kb = 0; kb < 128; kb += 32) {
        int kg = k0 + kb;
#pragma unroll
        for (int p = 0; p < 4; p++) {
            int i = t + p * 256;
            As[i & 31][i >> 5] = A[(i >> 5) * FF + kg + (i & 31)];
        }
#pragma unroll
        for (int p = 0; p < 4; p++) {
            int i = t + p * 256;
            int kk = i >> 5, nq = i & 31;
            *(float4*)&Ws[kk][nq * 4] = *(const float4*)&W[(kg + kk) * DD + nq * 4];
        }
        __syncthreads();
#pragma unroll
        for (int kk = 0; kk < 32; kk++) {
            float4 a = *(float4*)&As[kk][mi * 4];
            float4 w = *(float4*)&Ws[kk][ni * 4];
            acc[0][0] += a.x*w.x; acc[0][1] += a.x*w.y; acc[0][2] += a.x*w.z; acc[0][3] += a.x*w.w;
            acc[1][0] += a.y*w.x; acc[1][1] += a.y*w.y; acc[1][2] += a.y*w.z; acc[1][3] += a.y*w.w;
            acc[2][0] += a.z*w.x; acc[2][1] += a.z*w.y; acc[2][2] += a.z*w.z; acc[2][3] += a.z*w.w;
            acc[3][0] += a.w*w.x; acc[3][1] += a.w*w.y; acc[3][2] += a.w*w.z; acc[3][3] += a.w*w.w;
        }
        __syncthreads();
    }
#pragma unroll
    for (int i = 0; i < 4; i++)
#pragma unroll
        for (int j = 0; j < 4; j++)
            atomicAdd(&C[(mi * 4 + i) * DD + ni * 4 + j], acc[i][j]);
}

/* ---------------- flash-decode attention v3 --------------------------------
 * grid (B, 32), 256 thr = 8 warps; CH = tile = 256 l -> exactly <=1 tile.
 * K/V staged in two shared 64-l window buffers (cp.async ring:
 * K0,K1,K2,K3,V0,V1,V2,V3), all warps share each window.
 * QK: warp w -> l-cols [8w,8w+8) per window. PV: warp w -> d [16w,16w+16).
 * q: 2-term tf32 fragments, swizzled for conflict-free LDS.128.
 * smem floats: qfh 4096 | qfl 4096 | psh 32*260 | buf[2]*9216 = 139776 B  */
__global__ __launch_bounds__(256) void attn_kernel(
        const float* __restrict__ Kc, const float* __restrict__ Vc,
        const int* __restrict__ ci) {
    extern __shared__ float sm[];
    float4* qfh4 = (float4*)sm;
    float4* qfl4 = qfh4 + 1024;
    float*  psh  = sm + 8192;
    float*  bufs = sm + 8192 + 32 * LDP;     /* 2 x BUFF */

    int b = blockIdx.x, sp = blockIdx.y;
    int idx = ci[b];
    int c0  = sp * CH;
    if (c0 > idx) return;                    /* idle split */

    int t = threadIdx.x, w = t >> 5, lane = t & 31;
    int g = lane >> 2, c = lane & 3;
    float pos = (float)idx;

    const float* Kb = Kc + (size_t)b * DD * LL;
    const float* Vb = Vc + (size_t)b * DD * LL;

    auto fillK = [&](int wi, int bi) {
        uint32_t dst = s2u(bufs + bi * BUFF);
        const float* src = Kb + c0 + wi * WIN;
#pragma unroll
        for (int p = 0; p < 8; p++) {
            int i = t + p * 256; int d = i >> 4, u = i & 15;
            cpa16(dst + (uint32_t)(d * LDW + 4 * u) * 4, src + (size_t)d * LL + 4 * u);
        }
        cpcommit();
    };
    auto fillV = [&](int wi, int bi) {
        uint32_t dst = s2u(bufs + bi * BUFF);
        const float* src = Vb + c0 + wi * WIN;
#pragma unroll
        for (int p = 0; p < 8; p++) {
            int i = t + p * 256; int d = i >> 4, u = i & 15;
            cpa16(dst + (uint32_t)(d * LDV + 4 * u) * 4, src + (size_t)d * LL + 4 * u);
        }
        cpcommit();
    };

    fillK(0, 0);
    fillK(1, 1);

    /* q -> rope -> scale -> 2-term split -> swizzled fragment layout */
#pragma unroll
    for (int p = 0; p < 4; p++) {
        int fid = p * 256 + t;
        int kd = fid >> 6, mt = (fid >> 5) & 1, cc = (fid >> 3) & 3, gg = fid & 7;
        int r0 = mt * 16 + gg, r1 = r0 + 8;
        const float* qb = g_q + b * HH * DD;
        float4 hi, lo;
        float e[4];
#pragma unroll
        for (int dj = 0; dj < 2; dj++) {
            int dcol = 8 * kd + cc + 4 * dj;
            float si, co;
            sincosf(pos * g_freq[dcol & 63], &si, &co);
#pragma unroll
            for (int rj = 0; rj < 2; rj++) {
                int r = rj ? r1 : r0;
                float a = qb[r * DD + dcol];
                float o = qb[r * DD + (dcol ^ 64)];
                float v = (dcol < 64) ? (a * co - o * si) : (a * co + o * si);
                e[dj * 2 + rj] = v * SCALE;
            }
        }
        hi.x = tff(e[0]); lo.x = tff(e[0] - hi.x);
        hi.y = tff(e[1]); lo.y = tff(e[1] - hi.y);
        hi.z = tff(e[2]); lo.z = tff(e[2] - hi.z);
        hi.w = tff(e[3]); lo.w = tff(e[3] - hi.w);
        int sfid = kd * 64 + mt * 32 + cc * 8 + ((gg + 2 * cc) & 7);
        qfh4[sfid] = hi;
        qfl4[sfid] = lo;
    }
    __syncthreads();

    int swz = c * 8 + ((g + 2 * c) & 7);

    /* ---- QK over 4 windows ---- */
    for (int wi = 0; wi < 4; wi++) {
        cpwait1();
        __syncthreads();
        int l0w = c0 + wi * WIN;
        float* kb = bufs + (wi & 1) * BUFF;
        if (idx >= l0w && idx < l0w + WIN) {
            if (t < 128) {
                float si, co;
                sincosf(pos * g_freq[t & 63], &si, &co);
                float a = g_k[b * DD + t];
                float o = g_k[b * DD + (t ^ 64)];
                float kr = (t < 64) ? (a * co - o * si) : (a * co + o * si);
                kb[t * LDW + (idx - l0w)] += kr;
            }
            __syncthreads();
        }

        float accq[2][4];
#pragma unroll
        for (int mt = 0; mt < 2; mt++)
#pragma unroll
            for (int r = 0; r < 4; r++) accq[mt][r] = 0.f;

#pragma unroll
        for (int kd = 0; kd < 16; kd++) {
            float4 ah0 = qfh4[kd * 64 +      swz];
            float4 ah1 = qfh4[kd * 64 + 32 + swz];
            float4 al0 = qfl4[kd * 64 +      swz];
            float4 al1 = qfl4[kd * 64 + 32 + swz];
            float b0 = kb[(kd * 8 + c)     * LDW + w * 8 + g];
            float b1 = kb[(kd * 8 + c + 4) * LDW + w * 8 + g];
            uint32_t bb[2] = {f2tf(b0), f2tf(b1)};
            mma8(accq[0], (const uint32_t*)&ah0, bb);
            mma8(accq[0], (const uint32_t*)&al0, bb);
            mma8(accq[1], (const uint32_t*)&ah1, bb);
            mma8(accq[1], (const uint32_t*)&al1, bb);
        }
#pragma unroll
        for (int mt = 0; mt < 2; mt++) {
            int r0 = mt * 16 + g, cb = wi * 64 + w * 8 + 2 * c;
            psh[r0 * LDP + cb]           = accq[mt][0];
            psh[r0 * LDP + cb + 1]       = accq[mt][1];
            psh[(r0 + 8) * LDP + cb]     = accq[mt][2];
            psh[(r0 + 8) * LDP + cb + 1] = accq[mt][3];
        }
        __syncthreads();
        if (wi < 2) fillK(wi + 2, wi & 1);
        else        fillV(wi - 2, wi & 1);
    }

    /* ---- softmax: warp w owns heads 4w..4w+3; lane covers l = 8*lane ---- */
    int pb = (b * NSPLIT + sp) * HH;
#pragma unroll
    for (int hj = 0; hj < 4; hj++) {
        int h = 4 * w + hj;
        float4 fa = *(float4*)&psh[h * LDP + 8 * lane];
        float4 fb = *(float4*)&psh[h * LDP + 8 * lane + 4];
        if (c0 + CH - 1 > idx) {
            int lb = c0 + 8 * lane;
            if (lb     > idx) fa.x = -1e30f;
            if (lb + 1 > idx) fa.y = -1e30f;
            if (lb + 2 > idx) fa.z = -1e30f;
            if (lb + 3 > idx) fa.w = -1e30f;
            if (lb + 4 > idx) fb.x = -1e30f;
            if (lb + 5 > idx) fb.y = -1e30f;
            if (lb + 6 > idx) fb.z = -1e30f;
            if (lb + 7 > idx) fb.w = -1e30f;
        }
        float tm = fmaxf(fmaxf(fmaxf(fa.x, fa.y), fmaxf(fa.z, fa.w)),
                         fmaxf(fmaxf(fb.x, fb.y), fmaxf(fb.z, fb.w)));
        tm = fmaxf(tm, __shfl_xor_sync(0xffffffffu, tm, 16));
        tm = fmaxf(tm, __shfl_xor_sync(0xffffffffu, tm, 8));
        tm = fmaxf(tm, __shfl_xor_sync(0xffffffffu, tm, 4));
        tm = fmaxf(tm, __shfl_xor_sync(0xffffffffu, tm, 2));
        tm = fmaxf(tm, __shfl_xor_sync(0xffffffffu, tm, 1));
        float4 pa, pbv;
        pa.x  = __expf(fa.x - tm); pa.y  = __expf(fa.y - tm);
        pa.z  = __expf(fa.z - tm); pa.w  = __expf(fa.w - tm);
        pbv.x = __expf(fb.x - tm); pbv.y = __expf(fb.y - tm);
        pbv.z = __expf(fb.z - tm); pbv.w = __expf(fb.w - tm);
        float ls = (pa.x + pa.y + pa.z + pa.w) + (pbv.x + pbv.y + pbv.z + pbv.w);
        ls += __shfl_xor_sync(0xffffffffu, ls, 16);
        ls += __shfl_xor_sync(0xffffffffu, ls, 8);
        ls += __shfl_xor_sync(0xffffffffu, ls, 4);
        ls += __shfl_xor_sync(0xffffffffu, ls, 2);
        ls += __shfl_xor_sync(0xffffffffu, ls, 1);
        pa.x = tff(pa.x); pa.y = tff(pa.y); pa.z = tff(pa.z); pa.w = tff(pa.w);
        pbv.x = tff(pbv.x); pbv.y = tff(pbv.y); pbv.z = tff(pbv.z); pbv.w = tff(pbv.w);
        *(float4*)&psh[h * LDP + 8 * lane]     = pa;
        *(float4*)&psh[h * LDP + 8 * lane + 4] = pbv;
        if (lane == 0) { g_pm[pb + h] = tm; g_psum[pb + h] = ls; }
    }
    __syncthreads();

    /* ---- PV over 4 windows ---- */
    float acco[2][2][4];
#pragma unroll
    for (int mt = 0; mt < 2; mt++)
#pragma unroll
        for (int nt = 0; nt < 2; nt++)
#pragma unroll
            for (int r = 0; r < 4; r++) acco[mt][nt][r] = 0.f;

    for (int wi = 0; wi < 4; wi++) {
        if (wi == 3) cpwait0(); else cpwait1();
        __syncthreads();
        int l0w = c0 + wi * WIN;
        float* vb = bufs + (wi & 1) * BUFF;
        if (idx >= l0w && idx < l0w + WIN) {
            if (t < 128) vb[t * LDV + (idx - l0w)] += g_v[b * DD + t];
            __syncthreads();
        }

#pragma unroll
        for (int kl = 0; kl < 8; kl++) {
            int lb0 = wi * 64 + kl * 8 + c;
            uint32_t ap0[4], ap1[4];
            ap0[0] = __float_as_uint(psh[(g)      * LDP + lb0]);
            ap0[1] = __float_as_uint(psh[(g + 8)  * LDP + lb0]);
            ap0[2] = __float_as_uint(psh[(g)      * LDP + lb0 + 4]);
            ap0[3] = __float_as_uint(psh[(g + 8)  * LDP + lb0 + 4]);
            ap1[0] = __float_as_uint(psh[(g + 16) * LDP + lb0]);
            ap1[1] = __float_as_uint(psh[(g + 24) * LDP + lb0]);
            ap1[2] = __float_as_uint(psh[(g + 16) * LDP + lb0 + 4]);
            ap1[3] = __float_as_uint(psh[(g + 24) * LDP + lb0 + 4]);
#pragma unroll
            for (int nt = 0; nt < 2; nt++) {
                int d = w * 16 + nt * 8 + g;
                float v0 = vb[d * LDV + kl * 8 + c];
                float v1 = vb[d * LDV + kl * 8 + c + 4];
                uint32_t bh[2], bl[2];
                bh[0] = f2tf(v0); bl[0] = f2tf(v0 - __uint_as_float(bh[0]));
                bh[1] = f2tf(v1); bl[1] = f2tf(v1 - __uint_as_float(bh[1]));
                mma8(acco[0][nt], ap0, bh);
                mma8(acco[0][nt], ap0, bl);
                mma8(acco[1][nt], ap1, bh);
                mma8(acco[1][nt], ap1, bl);
            }
        }
        __syncthreads();
        if (wi < 2) fillV(wi + 2, wi & 1);
    }

    /* write un-normalized partials */
#pragma unroll
    for (int mt = 0; mt < 2; mt++)
#pragma unroll
        for (int nt = 0; nt < 2; nt++) {
            int h0 = mt * 16 + g;
            int dd = w * 16 + nt * 8 + 2 * c;
            g_po[(size_t)(pb + h0) * DD + dd]         = acco[mt][nt][0];
            g_po[(size_t)(pb + h0) * DD + dd + 1]     = acco[mt][nt][1];
            g_po[(size_t)(pb + h0 + 8) * DD + dd]     = acco[mt][nt][2];
            g_po[(size_t)(pb + h0 + 8) * DD + dd + 1] = acco[mt][nt][3];
        }
}

/* ---------------- combine (validity-aware) ------------------------------- */
__global__ void combine_kernel(const int* __restrict__ ci) {
    int bh = blockIdx.x;
    int b = bh >> 5, h = bh & 31;
    int d = threadIdx.x;
    int nv = (ci[b] >> 8) + 1;          /* # valid splits */
    float m = -1e30f;
    for (int s = 0; s < nv; s++)
        m = fmaxf(m, g_pm[(b * NSPLIT + s) * HH + h]);
    float S = 0.f, acc = 0.f;
    for (int s = 0; s < nv; s++) {
        int ib = (b * NSPLIT + s) * HH + h;
        float w = __expf(g_pm[ib] - m);
        S   += w * g_psum[ib];
        acc += w * g_po[(size_t)ib * DD + d];
    }
    g_attn[(b * HH + h) * DD + d] = acc / S;
}

/* ---------------- launch ------------------------------------------------- */
extern "C" void kernel_launch(void* const* d_in, const int* in_sizes, int n_in,
                              void* d_out, int out_size) {
    const float* x  = (const float*)d_in[0];
    const float* Kc = (const float*)d_in[1];
    const float* Vc = (const float*)d_in[2];
    const float* Wq = (const float*)d_in[3];
    const float* Wk = (const float*)d_in[4];
    const float* Wv = (const float*)d_in[5];
    const float* Wo = (const float*)d_in[6];
    const int*   ci = (const int*)d_in[7];
    float* out = (float*)d_out;

    float *qp, *ap;
    cudaGetSymbolAddress((void**)&qp, g_q);
    cudaGetSymbolAddress((void**)&ap, g_attn);

    cudaFuncSetAttribute(tgemm32,
                         cudaFuncAttributeMaxDynamicSharedMemorySize, 135168);
    cudaFuncSetAttribute(attn_kernel,
                         cudaFuncAttributeMaxDynamicSharedMemorySize, 139776);

    zero_kernel<<<512, 256>>>(out);
    tgemm32<<<dim3(16, SPLITK), 256, 135168>>>(x, Wq, qp, 4096);
    kvproj<<<dim3(2, 32), 256>>>(x, Wk, Wv);
    attn_kernel<<<dim3(32, NSPLIT), 256, 139776>>>(Kc, Vc, ci);
    combine_kernel<<<1024, 128>>>(ci);
    tgemm32<<<dim3(16, SPLITK), 256, 135168>>>(ap, Wo, out, 4096);
}

// round 8
// speedup vs baseline: 1.3141x; 1.0412x over previous
#include <cuda_runtime.h>
#include <math.h>
#include <stdint.h>

#define BB 32
#define FF 4096
#define HH 32
#define DD 128
#define LL 8192
#define NSPLIT 32
#define CH (LL/NSPLIT)          /* 256 */
#define WIN 64
#define LDW 72                  /* K window stride (floats) */
#define LDV 68                  /* V window stride (floats) */
#define LDP 68                  /* psh row stride (col 64 = corr) */
#define SCALE 0.08838834764831845f

/* ---------------- scratch ------------------------------------------------ */
__device__ float g_q[BB*HH*DD];
__device__ float g_k[BB*DD];
__device__ float g_v[BB*DD];
__device__ float g_attn[BB*HH*DD];
__device__ float g_pm[BB*NSPLIT*HH];
__device__ float g_psum[BB*NSPLIT*HH];
__device__ float g_po[BB*NSPLIT*HH*DD];
__device__ float g_freq[64];

/* ---------------- helpers ------------------------------------------------ */
__device__ __forceinline__ uint32_t s2u(const void* p) {
    return (uint32_t)__cvta_generic_to_shared(p);
}
__device__ __forceinline__ void cpa16(uint32_t s, const void* g) {
    asm volatile("cp.async.cg.shared.global [%0], [%1], 16;" :: "r"(s), "l"(g));
}
__device__ __forceinline__ void cpcommit() { asm volatile("cp.async.commit_group;"); }
__device__ __forceinline__ void cpwait0()  { asm volatile("cp.async.wait_group 0;"); }
__device__ __forceinline__ void cpwait1()  { asm volatile("cp.async.wait_group 1;"); }

__device__ __forceinline__ uint32_t f2tf(float x) {
    uint32_t r; asm("cvt.rna.tf32.f32 %0, %1;" : "=r"(r) : "f"(x)); return r;
}
__device__ __forceinline__ float tff(float x) { return __uint_as_float(f2tf(x)); }
__device__ __forceinline__ void mma8(float* d, const uint32_t* a, const uint32_t* b) {
    asm volatile("mma.sync.aligned.m16n8k8.row.col.f32.tf32.tf32.f32 "
        "{%0,%1,%2,%3},{%4,%5,%6,%7},{%8,%9},{%0,%1,%2,%3};"
        : "+f"(d[0]), "+f"(d[1]), "+f"(d[2]), "+f"(d[3])
        : "r"(a[0]), "r"(a[1]), "r"(a[2]), "r"(a[3]), "r"(b[0]), "r"(b[1]));
}

/* ---------------- zero + freq table -------------------------------------- */
__global__ void zero_kernel(float* __restrict__ out) {
    int i = blockIdx.x * 256 + threadIdx.x;
    g_q[i] = 0.f;
    out[i] = 0.f;
    if (i < BB*DD) { g_k[i] = 0.f; g_v[i] = 0.f; }
    if (i < 64) g_freq[i] = (float)exp(-(double)i * 0.14391156831212787);
}

/* ---------------- tensor GEMM (3xTF32, 3-stage): C += A[32,4096]*W -------- */
#define SPLITK 8
#define KSL (FF/SPLITK)
__global__ __launch_bounds__(256) void tgemm32(
        const float* __restrict__ A, const float* __restrict__ W,
        float* __restrict__ C, int N) {
    extern __shared__ float sm[];
    float* As = sm;                  /* 16896 floats */
    float* Ws = sm + 16896;          /* 3 x 8448 floats */
    uint32_t ws_u = s2u(Ws);

    int n0 = blockIdx.x * 256;
    int k0 = blockIdx.y * KSL;
    int t = threadIdx.x, wp = t >> 5, lane = t & 31;
    int g = lane >> 2, c = lane & 3;

#pragma unroll
    for (int p = 0; p < 64; p++) {
        int i = t + p * 256;
        int m = i >> 9, k = i & 511;
        As[k * 33 + m] = A[m * FF + k0 + k];
    }
    auto loadW = [&](int kb, int buf) {
        const float* src = W + (size_t)(k0 + kb * 32) * N + n0;
#pragma unroll
        for (int p = 0; p < 8; p++) {
            int ci = t + p * 256;
            int kk = ci >> 6, u = ci & 63;
            cpa16(ws_u + (uint32_t)(buf * 8448 + kk * 264 + 4 * u) * 4,
                  src + (size_t)kk * N + 4 * u);
        }
        cpcommit();
    };
    loadW(0, 0);
    loadW(1, 1);

    float acc[2][4][4];
#pragma unroll
    for (int mt = 0; mt < 2; mt++)
#pragma unroll
        for (int nt = 0; nt < 4; nt++)
#pragma unroll
            for (int r = 0; r < 4; r++) acc[mt][nt][r] = 0.f;

    for (int kb = 0; kb < 16; kb++) {
        if (kb == 15) cpwait0(); else cpwait1();
        __syncthreads();
        if (kb < 14) loadW(kb + 2, (kb + 2) % 3);
        const float* wsb = Ws + (kb % 3) * 8448;

#pragma unroll
        for (int ks = 0; ks < 4; ks++) {
            int kg = kb * 32 + ks * 8;
            uint32_t ahi[2][4], alo[2][4];
#pragma unroll
            for (int mt = 0; mt < 2; mt++) {
                float a0 = As[(kg + c)     * 33 + mt * 16 + g];
                float a1 = As[(kg + c)     * 33 + mt * 16 + g + 8];
                float a2 = As[(kg + c + 4) * 33 + mt * 16 + g];
                float a3 = As[(kg + c + 4) * 33 + mt * 16 + g + 8];
                ahi[mt][0] = f2tf(a0); alo[mt][0] = f2tf(a0 - __uint_as_float(ahi[mt][0]));
                ahi[mt][1] = f2tf(a1); alo[mt][1] = f2tf(a1 - __uint_as_float(ahi[mt][1]));
                ahi[mt][2] = f2tf(a2); alo[mt][2] = f2tf(a2 - __uint_as_float(ahi[mt][2]));
                ahi[mt][3] = f2tf(a3); alo[mt][3] = f2tf(a3 - __uint_as_float(ahi[mt][3]));
            }
#pragma unroll
            for (int nt = 0; nt < 4; nt++) {
                float b0 = wsb[(ks * 8 + c)     * 264 + wp * 32 + nt * 8 + g];
                float b1 = wsb[(ks * 8 + c + 4) * 264 + wp * 32 + nt * 8 + g];
                uint32_t bhi[2], blo[2];
                bhi[0] = f2tf(b0); blo[0] = f2tf(b0 - __uint_as_float(bhi[0]));
                bhi[1] = f2tf(b1); blo[1] = f2tf(b1 - __uint_as_float(bhi[1]));
#pragma unroll
                for (int mt = 0; mt < 2; mt++) {
                    mma8(acc[mt][nt], ahi[mt], bhi);
                    mma8(acc[mt][nt], ahi[mt], blo);
                    mma8(acc[mt][nt], alo[mt], bhi);
                }
            }
        }
    }
#pragma unroll
    for (int mt = 0; mt < 2; mt++)
#pragma unroll
        for (int nt = 0; nt < 4; nt++) {
            int row = mt * 16 + g;
            int col = n0 + wp * 32 + nt * 8 + 2 * c;
            atomicAdd(&C[(row)     * N + col],     acc[mt][nt][0]);
            atomicAdd(&C[(row)     * N + col + 1], acc[mt][nt][1]);
            atomicAdd(&C[(row + 8) * N + col],     acc[mt][nt][2]);
            atomicAdd(&C[(row + 8) * N + col + 1], acc[mt][nt][3]);
        }
}

/* ---------------- k/v projection ----------------------------------------- */
__global__ __launch_bounds__(256) void kvproj(
        const float* __restrict__ A, const float* __restrict__ Wk,
        const float* __restrict__ Wv) {
    __shared__ float As[32][36];
    __shared__ float Ws[32][132];
    const float* W = blockIdx.x ? Wv : Wk;
    float* C = blockIdx.x ? g_v : g_k;
    int k0 = blockIdx.y * 128;
    int t = threadIdx.x;
    int mi = t >> 5, ni = t & 31;
    float acc[4][4];
#pragma unroll
    for (int i = 0; i < 4; i++)
#pragma unroll
        for (int j = 0; j < 4; j++) acc[i][j] = 0.f;

    for (int kb = 0; kb < 128; kb += 32) {
        int kg = k0 + kb;
#pragma unroll
        for (int p = 0; p < 4; p++) {
            int i = t + p * 256;
            As[i & 31][i >> 5] = A[(i >> 5) * FF + kg + (i & 31)];
        }
#pragma unroll
        for (int p = 0; p < 4; p++) {
            int i = t + p * 256;
            int kk = i >> 5, nq = i & 31;
            *(float4*)&Ws[kk][nq * 4] = *(const float4*)&W[(kg + kk) * DD + nq * 4];
        }
        __syncthreads();
#pragma unroll
        for (int kk = 0; kk < 32; kk++) {
            float4 a = *(float4*)&As[kk][mi * 4];
            float4 w = *(float4*)&Ws[kk][ni * 4];
            acc[0][0] += a.x*w.x; acc[0][1] += a.x*w.y; acc[0][2] += a.x*w.z; acc[0][3] += a.x*w.w;
            acc[1][0] += a.y*w.x; acc[1][1] += a.y*w.y; acc[1][2] += a.y*w.z; acc[1][3] += a.y*w.w;
            acc[2][0] += a.z*w.x; acc[2][1] += a.z*w.y; acc[2][2] += a.z*w.z; acc[2][3] += a.z*w.w;
            acc[3][0] += a.w*w.x; acc[3][1] += a.w*w.y; acc[3][2] += a.w*w.z; acc[3][3] += a.w*w.w;
        }
        __syncthreads();
    }
#pragma unroll
    for (int i = 0; i < 4; i++)
#pragma unroll
        for (int j = 0; j < 4; j++)
            atomicAdd(&C[(mi * 4 + i) * DD + ni * 4 + j], acc[i][j]);
}

/* ---------------- flash-decode attention v4 --------------------------------
 * grid (B, 32), 256 thr = 8 warps, 2 CTAs/SM (smem 113,152 B).
 * Per 64-l window: QK -> online softmax -> PV, with cp.async ring
 * K0,V0,K1,V1,... through one K buffer (128x72) + one V buffer (128x68).
 * smem floats: qfh 4096 | qfl 4096 | psh 32x68 | kbuf 9216 | vbuf 8704    */
__global__ __launch_bounds__(256, 2) void attn_kernel(
        const float* __restrict__ Kc, const float* __restrict__ Vc,
        const int* __restrict__ ci) {
    extern __shared__ float sm[];
    float4* qfh4 = (float4*)sm;
    float4* qfl4 = qfh4 + 1024;
    float*  psh  = sm + 8192;
    float*  kbuf = sm + 10368;
    float*  vbuf = sm + 19584;

    int b = blockIdx.x, sp = blockIdx.y;
    int idx = ci[b];
    int c0  = sp * CH;
    if (c0 > idx) return;

    int t = threadIdx.x, w = t >> 5, lane = t & 31;
    int g = lane >> 2, c = lane & 3;
    float pos = (float)idx;

    const float* Kb = Kc + (size_t)b * DD * LL;
    const float* Vb = Vc + (size_t)b * DD * LL;

    auto fillK = [&](int wi) {
        uint32_t dst = s2u(kbuf);
        const float* src = Kb + c0 + wi * WIN;
#pragma unroll
        for (int p = 0; p < 8; p++) {
            int i = t + p * 256; int d = i >> 4, u = i & 15;
            cpa16(dst + (uint32_t)(d * LDW + 4 * u) * 4, src + (size_t)d * LL + 4 * u);
        }
        cpcommit();
    };
    auto fillV = [&](int wi) {
        uint32_t dst = s2u(vbuf);
        const float* src = Vb + c0 + wi * WIN;
#pragma unroll
        for (int p = 0; p < 8; p++) {
            int i = t + p * 256; int d = i >> 4, u = i & 15;
            cpa16(dst + (uint32_t)(d * LDV + 4 * u) * 4, src + (size_t)d * LL + 4 * u);
        }
        cpcommit();
    };

    fillK(0);
    fillV(0);

    /* q -> rope -> scale -> 2-term tf32, swizzled fragment layout */
#pragma unroll
    for (int p = 0; p < 4; p++) {
        int fid = p * 256 + t;
        int kd = fid >> 6, mt = (fid >> 5) & 1, cc = (fid >> 3) & 3, gg = fid & 7;
        int r0 = mt * 16 + gg, r1 = r0 + 8;
        const float* qb = g_q + b * HH * DD;
        float4 hi, lo;
        float e[4];
#pragma unroll
        for (int dj = 0; dj < 2; dj++) {
            int dcol = 8 * kd + cc + 4 * dj;
            float si, co;
            sincosf(pos * g_freq[dcol & 63], &si, &co);
#pragma unroll
            for (int rj = 0; rj < 2; rj++) {
                int r = rj ? r1 : r0;
                float a = qb[r * DD + dcol];
                float o = qb[r * DD + (dcol ^ 64)];
                float v = (dcol < 64) ? (a * co - o * si) : (a * co + o * si);
                e[dj * 2 + rj] = v * SCALE;
            }
        }
        hi.x = tff(e[0]); lo.x = tff(e[0] - hi.x);
        hi.y = tff(e[1]); lo.y = tff(e[1] - hi.y);
        hi.z = tff(e[2]); lo.z = tff(e[2] - hi.z);
        hi.w = tff(e[3]); lo.w = tff(e[3] - hi.w);
        int sfid = kd * 64 + mt * 32 + cc * 8 + ((gg + 2 * cc) & 7);
        qfh4[sfid] = hi;
        qfl4[sfid] = lo;
    }
    __syncthreads();

    int swz = c * 8 + ((g + 2 * c) & 7);

    float m_r[4] = {-1e30f, -1e30f, -1e30f, -1e30f};
    float s_r[4] = {0.f, 0.f, 0.f, 0.f};
    float acco[2][2][4];
#pragma unroll
    for (int mt = 0; mt < 2; mt++)
#pragma unroll
        for (int nt = 0; nt < 2; nt++)
#pragma unroll
            for (int r = 0; r < 4; r++) acco[mt][nt][r] = 0.f;

    for (int wi = 0; wi < 4; wi++) {
        int l0w = c0 + wi * WIN;
        int hot = (idx >= l0w) && (idx < l0w + WIN);
        int li = idx - l0w;

        cpwait1();                  /* K_wi done (V_wi still pending) */
        __syncthreads();
        if (hot) {
            if (t < 128) {
                float si, co;
                sincosf(pos * g_freq[t & 63], &si, &co);
                float a = g_k[b * DD + t];
                float o = g_k[b * DD + (t ^ 64)];
                float kr = (t < 64) ? (a * co - o * si) : (a * co + o * si);
                kbuf[t * LDW + li] += kr;
            }
            __syncthreads();
        }

        /* ---- QK: warp w -> window l-cols [8w, 8w+8) ---- */
        float accq[2][4];
#pragma unroll
        for (int mt = 0; mt < 2; mt++)
#pragma unroll
            for (int r = 0; r < 4; r++) accq[mt][r] = 0.f;

#pragma unroll
        for (int kd = 0; kd < 16; kd++) {
            float4 ah0 = qfh4[kd * 64 +      swz];
            float4 ah1 = qfh4[kd * 64 + 32 + swz];
            float4 al0 = qfl4[kd * 64 +      swz];
            float4 al1 = qfl4[kd * 64 + 32 + swz];
            float b0 = kbuf[(kd * 8 + c)     * LDW + w * 8 + g];
            float b1 = kbuf[(kd * 8 + c + 4) * LDW + w * 8 + g];
            uint32_t bb[2] = {f2tf(b0), f2tf(b1)};
            mma8(accq[0], (const uint32_t*)&ah0, bb);
            mma8(accq[0], (const uint32_t*)&al0, bb);
            mma8(accq[1], (const uint32_t*)&ah1, bb);
            mma8(accq[1], (const uint32_t*)&al1, bb);
        }
#pragma unroll
        for (int mt = 0; mt < 2; mt++) {
            int r0 = mt * 16 + g, cb = w * 8 + 2 * c;
            psh[r0 * LDP + cb]           = accq[mt][0];
            psh[r0 * LDP + cb + 1]       = accq[mt][1];
            psh[(r0 + 8) * LDP + cb]     = accq[mt][2];
            psh[(r0 + 8) * LDP + cb + 1] = accq[mt][3];
        }
        __syncthreads();            /* logits visible; kbuf free */
        if (wi < 3) fillK(wi + 1);

        /* ---- online softmax: warp w owns heads 4w..4w+3; lane -> l=2*lane */
#pragma unroll
        for (int hj = 0; hj < 4; hj++) {
            int h = 4 * w + hj;
            float2 f = *(float2*)&psh[h * LDP + 2 * lane];
            if (l0w + WIN - 1 > idx) {
                int lb = l0w + 2 * lane;
                if (lb     > idx) f.x = -1e30f;
                if (lb + 1 > idx) f.y = -1e30f;
            }
            float tm = fmaxf(f.x, f.y);
            tm = fmaxf(tm, __shfl_xor_sync(0xffffffffu, tm, 16));
            tm = fmaxf(tm, __shfl_xor_sync(0xffffffffu, tm, 8));
            tm = fmaxf(tm, __shfl_xor_sync(0xffffffffu, tm, 4));
            tm = fmaxf(tm, __shfl_xor_sync(0xffffffffu, tm, 2));
            tm = fmaxf(tm, __shfl_xor_sync(0xffffffffu, tm, 1));
            float mn = fmaxf(m_r[hj], tm);
            float co = __expf(m_r[hj] - mn);
            float p0 = __expf(f.x - mn), p1 = __expf(f.y - mn);
            float ls = p0 + p1;
            ls += __shfl_xor_sync(0xffffffffu, ls, 16);
            ls += __shfl_xor_sync(0xffffffffu, ls, 8);
            ls += __shfl_xor_sync(0xffffffffu, ls, 4);
            ls += __shfl_xor_sync(0xffffffffu, ls, 2);
            ls += __shfl_xor_sync(0xffffffffu, ls, 1);
            s_r[hj] = s_r[hj] * co + ls;
            m_r[hj] = mn;
            *(float2*)&psh[h * LDP + 2 * lane] = make_float2(tff(p0), tff(p1));
            if (lane == 0) psh[h * LDP + 64] = co;
        }

        if (wi == 3) cpwait0(); else cpwait1();   /* V_wi done */
        __syncthreads();            /* probs/corr visible; vbuf stable */
        if (hot) {
            if (t < 128) vbuf[t * LDV + li] += g_v[b * DD + t];
            __syncthreads();
        }

        /* rescale PV accumulators */
        {
            float s0 = psh[(g)      * LDP + 64];
            float s1 = psh[(g + 8)  * LDP + 64];
            float s2 = psh[(g + 16) * LDP + 64];
            float s3 = psh[(g + 24) * LDP + 64];
#pragma unroll
            for (int nt = 0; nt < 2; nt++) {
                acco[0][nt][0] *= s0; acco[0][nt][1] *= s0;
                acco[0][nt][2] *= s1; acco[0][nt][3] *= s1;
                acco[1][nt][0] *= s2; acco[1][nt][1] *= s2;
                acco[1][nt][2] *= s3; acco[1][nt][3] *= s3;
            }
        }

        /* ---- PV: warp w -> d [16w, 16w+16) ---- */
#pragma unroll
        for (int kl = 0; kl < 8; kl++) {
            int lb0 = kl * 8 + c;
            uint32_t ap0[4], ap1[4];
            ap0[0] = __float_as_uint(psh[(g)      * LDP + lb0]);
            ap0[1] = __float_as_uint(psh[(g + 8)  * LDP + lb0]);
            ap0[2] = __float_as_uint(psh[(g)      * LDP + lb0 + 4]);
            ap0[3] = __float_as_uint(psh[(g + 8)  * LDP + lb0 + 4]);
            ap1[0] = __float_as_uint(psh[(g + 16) * LDP + lb0]);
            ap1[1] = __float_as_uint(psh[(g + 24) * LDP + lb0]);
            ap1[2] = __float_as_uint(psh[(g + 16) * LDP + lb0 + 4]);
            ap1[3] = __float_as_uint(psh[(g + 24) * LDP + lb0 + 4]);
#pragma unroll
            for (int nt = 0; nt < 2; nt++) {
                int d = w * 16 + nt * 8 + g;
                float v0 = vbuf[d * LDV + kl * 8 + c];
                float v1 = vbuf[d * LDV + kl * 8 + c + 4];
                uint32_t bh[2], bl[2];
                bh[0] = f2tf(v0); bl[0] = f2tf(v0 - __uint_as_float(bh[0]));
                bh[1] = f2tf(v1); bl[1] = f2tf(v1 - __uint_as_float(bh[1]));
                mma8(acco[0][nt], ap0, bh);
                mma8(acco[0][nt], ap0, bl);
                mma8(acco[1][nt], ap1, bh);
                mma8(acco[1][nt], ap1, bl);
            }
        }
        __syncthreads();            /* vbuf + psh free */
        if (wi < 3) fillV(wi + 1);
    }

    /* write partials */
    int pb = (b * NSPLIT + sp) * HH;
    if (lane == 0) {
#pragma unroll
        for (int hj = 0; hj < 4; hj++) {
            g_pm[pb + 4 * w + hj]   = m_r[hj];
            g_psum[pb + 4 * w + hj] = s_r[hj];
        }
    }
#pragma unroll
    for (int mt = 0; mt < 2; mt++)
#pragma unroll
        for (int nt = 0; nt < 2; nt++) {
            int h0 = mt * 16 + g;
            int dd = w * 16 + nt * 8 + 2 * c;
            g_po[(size_t)(pb + h0) * DD + dd]         = acco[mt][nt][0];
            g_po[(size_t)(pb + h0) * DD + dd + 1]     = acco[mt][nt][1];
            g_po[(size_t)(pb + h0 + 8) * DD + dd]     = acco[mt][nt][2];
            g_po[(size_t)(pb + h0 + 8) * DD + dd + 1] = acco[mt][nt][3];
        }
}

/* ---------------- combine (validity-aware) ------------------------------- */
__global__ void combine_kernel(const int* __restrict__ ci) {
    int bh = blockIdx.x;
    int b = bh >> 5, h = bh & 31;
    int d = threadIdx.x;
    int nv = (ci[b] >> 8) + 1;
    float m = -1e30f;
    for (int s = 0; s < nv; s++)
        m = fmaxf(m, g_pm[(b * NSPLIT + s) * HH + h]);
    float S = 0.f, acc = 0.f;
    for (int s = 0; s < nv; s++) {
        int ib = (b * NSPLIT + s) * HH + h;
        float w = __expf(g_pm[ib] - m);
        S   += w * g_psum[ib];
        acc += w * g_po[(size_t)ib * DD + d];
    }
    g_attn[(b * HH + h) * DD + d] = acc / S;
}

/* ---------------- launch ------------------------------------------------- */
extern "C" void kernel_launch(void* const* d_in, const int* in_sizes, int n_in,
                              void* d_out, int out_size) {
    const float* x  = (const float*)d_in[0];
    const float* Kc = (const float*)d_in[1];
    const float* Vc = (const float*)d_in[2];
    const float* Wq = (const float*)d_in[3];
    const float* Wk = (const float*)d_in[4];
    const float* Wv = (const float*)d_in[5];
    const float* Wo = (const float*)d_in[6];
    const int*   ci = (const int*)d_in[7];
    float* out = (float*)d_out;

    float *qp, *ap;
    cudaGetSymbolAddress((void**)&qp, g_q);
    cudaGetSymbolAddress((void**)&ap, g_attn);

    cudaFuncSetAttribute(tgemm32,
                         cudaFuncAttributeMaxDynamicSharedMemorySize, 168960);
    cudaFuncSetAttribute(attn_kernel,
                         cudaFuncAttributeMaxDynamicSharedMemorySize, 113152);

    zero_kernel<<<512, 256>>>(out);
    tgemm32<<<dim3(16, SPLITK), 256, 168960>>>(x, Wq, qp, 4096);
    kvproj<<<dim3(2, 32), 256>>>(x, Wk, Wv);
    attn_kernel<<<dim3(32, NSPLIT), 256, 113152>>>(Kc, Vc, ci);
    combine_kernel<<<1024, 128>>>(ci);
    tgemm32<<<dim3(16, SPLITK), 256, 168960>>>(ap, Wo, out, 4096);
}